// round 13
// baseline (speedup 1.0000x reference)
#include <cuda_runtime.h>
#include <cuda_fp16.h>
#include <stdint.h>

#define NPTS 131072
#define NM   34
#define NK   15
#define CIN  32
#define COUT 64
#define KTOT 480                 // NK * CIN
#define INV_SIGMA 25.0f          // 1 / 0.04
#define BN_EPS 1e-5f
#define NEG_SLOPE 0.2f

#define PTS_BLK 128
#define NTHREADS 512
#define NWARPS 16
#define SA 488                   // As row stride in halves (bank-safe: 244 words, mod32=20)

// ---- dynamic smem layout (bytes) ----
#define OFF_AS   0                         // __half As[128][488]      = 124928
#define OFF_BH   124928                    // __half Bh[2][32][72]     =   9216
#define OFF_BL   134144                    // __half Bl[2][32][72]     =   9216
#define OFF_NB   143360                    // float4 nb[16][34]        =   8704
#define OFF_W    152064                    // float  w[16][544]        =  34816
#define OFF_IDX  186880                    // int    idx[16][34]       =   2176
#define OFF_ACT  189056                    // int    act[16][34]       =   2176
#define OFF_BN   191232                    // float  bn[128]           =    512
#define OFF_KC   191744                    // float4 kc[16]            =    256
#define SMEM_TOTAL 192000

// ---- device scratch (no allocations allowed) ----
__device__ __align__(16) __half g_wh_hi[KTOT * COUT];           // 60 KB
__device__ __align__(16) __half g_wh_lo[KTOT * COUT];           // 60 KB
__device__ __align__(16) float4 g_xyz4[NPTS];                   // 2 MB
__device__ float  g_raw[(size_t)NPTS * COUT];                   // 33.5 MB
__device__ float  g_accum[2 * COUT];

// ---- packed f32x2 helpers ----
__device__ __forceinline__ unsigned long long ffma2(unsigned long long a,
                                                    unsigned long long b,
                                                    unsigned long long c) {
    unsigned long long d;
    asm("fma.rn.f32x2 %0, %1, %2, %3;" : "=l"(d) : "l"(a), "l"(b), "l"(c));
    return d;
}
__device__ __forceinline__ unsigned long long pack2(float lo, float hi) {
    unsigned long long d;
    asm("mov.b64 %0, {%1, %2};" : "=l"(d) : "f"(lo), "f"(hi));
    return d;
}
__device__ __forceinline__ void unpack2(unsigned long long v, float& lo, float& hi) {
    asm("mov.b64 {%0, %1}, %2;" : "=f"(lo), "=f"(hi) : "l"(v));
}

// ---- tensor-core / async-copy helpers ----
__device__ __forceinline__ uint32_t smem_u32(const void* p) {
    return (uint32_t)__cvta_generic_to_shared(p);
}
__device__ __forceinline__ void cp16(uint32_t dst, const void* src) {
    asm volatile("cp.async.cg.shared.global [%0], [%1], 16;" :: "r"(dst), "l"(src));
}
#define CP_COMMIT() asm volatile("cp.async.commit_group;")
#define CP_WAIT(n)  asm volatile("cp.async.wait_group %0;" :: "n"(n))

__device__ __forceinline__ void ldm_x4(uint32_t& r0, uint32_t& r1,
                                       uint32_t& r2, uint32_t& r3, uint32_t addr) {
    asm volatile("ldmatrix.sync.aligned.m8n8.x4.shared.b16 {%0,%1,%2,%3}, [%4];"
                 : "=r"(r0), "=r"(r1), "=r"(r2), "=r"(r3) : "r"(addr));
}
__device__ __forceinline__ void ldm_x4_trans(uint32_t& r0, uint32_t& r1,
                                             uint32_t& r2, uint32_t& r3, uint32_t addr) {
    asm volatile("ldmatrix.sync.aligned.m8n8.x4.trans.shared.b16 {%0,%1,%2,%3}, [%4];"
                 : "=r"(r0), "=r"(r1), "=r"(r2), "=r"(r3) : "r"(addr));
}
__device__ __forceinline__ void mma16816(float& c0, float& c1, float& c2, float& c3,
                                         uint32_t a0, uint32_t a1, uint32_t a2, uint32_t a3,
                                         uint32_t b0, uint32_t b1) {
    asm volatile("mma.sync.aligned.m16n8k16.row.col.f32.f16.f16.f32 "
                 "{%0,%1,%2,%3}, {%4,%5,%6,%7}, {%8,%9}, {%0,%1,%2,%3};"
                 : "+f"(c0), "+f"(c1), "+f"(c2), "+f"(c3)
                 : "r"(a0), "r"(a1), "r"(a2), "r"(a3), "r"(b0), "r"(b1));
}

// ================= stage 0: repack xyz + split W + zero accum =================
__global__ __launch_bounds__(256)
void prep_kernel(const float* __restrict__ xyz,
                 const float* __restrict__ weight)
{
    const int b = blockIdx.x;
    if (b < NPTS / 256) {
        int n = b * 256 + threadIdx.x;
        g_xyz4[n] = make_float4(xyz[n * 3 + 0], xyz[n * 3 + 1], xyz[n * 3 + 2], 0.f);
    } else {
        int wb = b - NPTS / 256;                 // 0..7
        for (int j = 0; j < (KTOT * COUT) / (8 * 256); j++) {
            int i = (wb * (KTOT * COUT) / 8) + j * 256 + threadIdx.x;
            float w = weight[i];
            __half h = __float2half_rn(w);
            g_wh_hi[i] = h;
            g_wh_lo[i] = __float2half_rn(w - __half2float(h));
        }
        if (wb == 0 && threadIdx.x < 2 * COUT) g_accum[threadIdx.x] = 0.f;
    }
}

// ================= fused: wf (smem fp16) + HMMA GEMM + BN partials =================
__global__ __launch_bounds__(NTHREADS, 1)
void kpconv_fused(const float* __restrict__ feats,
                  const int*   __restrict__ nbr,
                  const float* __restrict__ kpts)
{
    extern __shared__ __align__(16) char smem[];
    __half* As      = (__half*)(smem + OFF_AS);
    float4* sm_kc   = (float4*)(smem + OFF_KC);
    float*  sm_bn   = (float*) (smem + OFF_BN);

    const int tid  = threadIdx.x;
    const int lane = tid & 31;
    const int warp = tid >> 5;
    const int row0 = blockIdx.x * PTS_BLK;

    float4* nbw  = (float4*)(smem + OFF_NB)  + warp * NM;
    int*    idxw = (int*)   (smem + OFF_IDX) + warp * NM;
    int*    actw = (int*)   (smem + OFF_ACT) + warp * NM;
    float*  ww   = (float*) (smem + OFF_W)   + warp * 544;

    // ---- prefetch first B chunk (overlaps all of stage A) ----
    {
        int plane = tid >> 8, idx = tid & 255;
        int r = idx >> 3, q = idx & 7;
        uint32_t dst = smem_u32(smem + (plane ? OFF_BL : OFF_BH) + (r * 72 + q * 8) * 2);
        const __half* src = (plane ? g_wh_lo : g_wh_hi) + r * COUT + q * 8;
        cp16(dst, src);
        CP_COMMIT();
    }

    if (tid < 16) {
        float4 kc = make_float4(0.f, 0.f, 0.f, 0.f);
        if (tid < NK) {
            kc.x = kpts[tid * 3 + 0];
            kc.y = kpts[tid * 3 + 1];
            kc.z = kpts[tid * 3 + 2];
        }
        sm_kc[tid] = kc;
    }
    if (tid < 2 * COUT) sm_bn[tid] = 0.f;
    __syncthreads();

    // =================== stage A: wf -> As (fp16) ===================
    for (int i = 0; i < 8; i++) {
        const int pt = warp * 8 + i;
        const int n  = row0 + pt;

        const float4 c4 = g_xyz4[n];

        #pragma unroll
        for (int j = 0; j < 2; j++) {
            int m = j * 32 + lane;
            if (m < NM) {
                int idx = nbr[n * NM + m];
                int ci  = (idx < NPTS) ? idx : 0;          // shadow guard
                float4 p = __ldg(&g_xyz4[ci]);
                float4 v = make_float4(p.x - c4.x, p.y - c4.y, p.z - c4.z, 0.f);
                if (idx >= NPTS) { v.x = 1e6f; v.y = 1e6f; v.z = 1e6f; }
                nbw[m]  = v;
                idxw[m] = ci;
            }
        }
        __syncwarp();

        // influence weights w[m*16+k] + per-m activity mask
        #pragma unroll
        for (int it = 0; it < 17; it++) {
            int p = it * 32 + lane;                        // 0..543
            int m = p >> 4;
            int k = p & 15;
            float4 nb = nbw[m];
            float4 kc = sm_kc[k];
            float dx = nb.x - kc.x;
            float dy = nb.y - kc.y;
            float dz = nb.z - kc.z;
            float d2 = fmaf(dx, dx, fmaf(dy, dy, dz * dz));
            float w  = fmaf(sqrtf(d2), -INV_SIGMA, 1.f);
            bool on  = (w > 0.f) && (k < 15);
            unsigned bal = __ballot_sync(0xffffffffu, on);
            ww[p] = on ? w : 0.f;
            if (lane == 0)  actw[it * 2]     = (int)(bal & 0xffffu);
            if (lane == 16) actw[it * 2 + 1] = (int)(bal >> 16);
        }
        __syncwarp();

        // wf accumulation — gated in-loop loads
        unsigned long long wf2[8];
        #pragma unroll
        for (int j = 0; j < 8; j++) wf2[j] = 0ull;

        #pragma unroll 2
        for (int m = 0; m < NM; m++) {
            if (actw[m] == 0) continue;
            int ci  = idxw[m];
            float f = __ldg(&feats[(size_t)ci * CIN + lane]);
            unsigned long long ff = pack2(f, f);
            const unsigned long long* wp = (const unsigned long long*)&ww[m * 16];
            #pragma unroll
            for (int j = 0; j < 8; j++)
                wf2[j] = ffma2(ff, wp[j], wf2[j]);
        }

        // fp16 store to As (k-major: col = k*32 + lane)
        __half* dh = &As[pt * SA + lane];
        #pragma unroll
        for (int j = 0; j < 8; j++) {
            float a, b;
            unpack2(wf2[j], a, b);
            dh[(2 * j) * 32] = __float2half_rn(a);
            if (j < 7) dh[(2 * j + 1) * 32] = __float2half_rn(b);
        }
        __syncwarp();
    }
    __syncthreads();

    // =================== stage B: GEMM As[128][480] @ W[480][64] ===================
    const int warpM = warp >> 1;            // 0..7: 16-row group
    const int nhalf = warp & 1;             // 0/1:  32-col half

    float acc[4][4];
    #pragma unroll
    for (int nt = 0; nt < 4; nt++)
        #pragma unroll
        for (int c = 0; c < 4; c++) acc[nt][c] = 0.f;

    const int arow = warpM * 16 + (lane & 15);
    const uint32_t aBase = smem_u32(&As[arow * SA + (lane >> 4) * 8]);
    const int brow = ((lane >> 3) & 1) * 8 + (lane & 7);
    const int bcol = nhalf * 32 + (lane >> 4) * 8;
    const uint32_t bhBase = smem_u32(smem + OFF_BH + (brow * 72 + bcol) * 2);
    const uint32_t blBase = smem_u32(smem + OFF_BL + (brow * 72 + bcol) * 2);

    const int plane = tid >> 8, bidx = tid & 255;
    const int br = bidx >> 3, bq = bidx & 7;
    const uint32_t bDstBase = smem_u32(smem + (plane ? OFF_BL : OFF_BH) + (br * 72 + bq * 8) * 2);
    const __half* bSrcBase = (plane ? g_wh_lo : g_wh_hi) + br * COUT + bq * 8;

    for (int kc = 0; kc < KTOT / 32; kc++) {
        const int buf = kc & 1;
        if (kc < KTOT / 32 - 1) {
            cp16(bDstBase + (buf ^ 1) * 4608, bSrcBase + (size_t)(kc + 1) * 32 * COUT);
            CP_COMMIT();
            CP_WAIT(1);
        } else {
            CP_WAIT(0);
        }
        __syncthreads();

        #pragma unroll
        for (int ks = 0; ks < 2; ks++) {
            uint32_t ah[4];
            ldm_x4(ah[0], ah[1], ah[2], ah[3], aBase + kc * 64 + ks * 32);

            uint32_t bh[4][2], bl[4][2];
            #pragma unroll
            for (int np = 0; np < 2; np++) {
                uint32_t r0, r1, r2, r3;
                ldm_x4_trans(r0, r1, r2, r3, bhBase + buf * 4608 + ks * 2304 + np * 32);
                bh[2 * np][0] = r0; bh[2 * np][1] = r1;
                bh[2 * np + 1][0] = r2; bh[2 * np + 1][1] = r3;
                ldm_x4_trans(r0, r1, r2, r3, blBase + buf * 4608 + ks * 2304 + np * 32);
                bl[2 * np][0] = r0; bl[2 * np][1] = r1;
                bl[2 * np + 1][0] = r2; bl[2 * np + 1][1] = r3;
            }
            #pragma unroll
            for (int nt = 0; nt < 4; nt++) {
                mma16816(acc[nt][0], acc[nt][1], acc[nt][2], acc[nt][3],
                         ah[0], ah[1], ah[2], ah[3], bh[nt][0], bh[nt][1]);
                mma16816(acc[nt][0], acc[nt][1], acc[nt][2], acc[nt][3],
                         ah[0], ah[1], ah[2], ah[3], bl[nt][0], bl[nt][1]);
            }
        }
        __syncthreads();
    }

    // epilogue: write raw out + BN partial sums
    const int g8 = lane >> 2, t4 = lane & 3;
    const int rA = row0 + warpM * 16 + g8;
    const int rB = rA + 8;
    float lsum[8], lsq[8];
    #pragma unroll
    for (int nt = 0; nt < 4; nt++) {
        int col = nhalf * 32 + nt * 8 + 2 * t4;
        *(float2*)&g_raw[(size_t)rA * COUT + col] = make_float2(acc[nt][0], acc[nt][1]);
        *(float2*)&g_raw[(size_t)rB * COUT + col] = make_float2(acc[nt][2], acc[nt][3]);
        lsum[2 * nt]     = acc[nt][0] + acc[nt][2];
        lsum[2 * nt + 1] = acc[nt][1] + acc[nt][3];
        lsq[2 * nt]      = fmaf(acc[nt][0], acc[nt][0], acc[nt][2] * acc[nt][2]);
        lsq[2 * nt + 1]  = fmaf(acc[nt][1], acc[nt][1], acc[nt][3] * acc[nt][3]);
    }
    #pragma unroll
    for (int mask = 4; mask <= 16; mask <<= 1) {
        #pragma unroll
        for (int v = 0; v < 8; v++) {
            lsum[v] += __shfl_xor_sync(0xffffffffu, lsum[v], mask);
            lsq[v]  += __shfl_xor_sync(0xffffffffu, lsq[v],  mask);
        }
    }
    if (g8 == 0) {
        #pragma unroll
        for (int nt = 0; nt < 4; nt++) {
            int col = nhalf * 32 + nt * 8 + 2 * t4;
            atomicAdd(&sm_bn[col],            lsum[2 * nt]);
            atomicAdd(&sm_bn[col + 1],        lsum[2 * nt + 1]);
            atomicAdd(&sm_bn[COUT + col],     lsq[2 * nt]);
            atomicAdd(&sm_bn[COUT + col + 1], lsq[2 * nt + 1]);
        }
    }
    __syncthreads();
    if (tid < 2 * COUT) atomicAdd(&g_accum[tid], sm_bn[tid]);
}

// ================= finalize (computes BN params per-block) =================
__global__ __launch_bounds__(256)
void finalize_kernel(float* __restrict__ out,
                     const float* __restrict__ gamma,
                     const float* __restrict__ beta)
{
    __shared__ float sp[2 * COUT];
    const int t = threadIdx.x;
    if (t < COUT) {
        const float invN = 1.0f / (float)NPTS;
        float mean = g_accum[t] * invN;
        float var  = g_accum[COUT + t] * invN - mean * mean;
        float inv  = rsqrtf(var + BN_EPS);
        float sc   = gamma[t] * inv;
        sp[t]        = sc;
        sp[COUT + t] = fmaf(-mean, sc, beta[t]);
    }
    __syncthreads();

    int i = blockIdx.x * blockDim.x + t;             // over N*64/4 float4s
    float4 v = *(const float4*)&g_raw[(size_t)i * 4];
    int d4 = (i & 15) * 4;
    float x0 = fmaf(v.x, sp[d4 + 0], sp[COUT + d4 + 0]);
    float x1 = fmaf(v.y, sp[d4 + 1], sp[COUT + d4 + 1]);
    float x2 = fmaf(v.z, sp[d4 + 2], sp[COUT + d4 + 2]);
    float x3 = fmaf(v.w, sp[d4 + 3], sp[COUT + d4 + 3]);
    x0 = (x0 >= 0.f) ? x0 : NEG_SLOPE * x0;
    x1 = (x1 >= 0.f) ? x1 : NEG_SLOPE * x1;
    x2 = (x2 >= 0.f) ? x2 : NEG_SLOPE * x2;
    x3 = (x3 >= 0.f) ? x3 : NEG_SLOPE * x3;
    ((float4*)out)[i] = make_float4(x0, x1, x2, x3);
}

extern "C" void kernel_launch(void* const* d_in, const int* in_sizes, int n_in,
                              void* d_out, int out_size)
{
    const float* xyz    = (const float*)d_in[0];
    const float* feats  = (const float*)d_in[1];
    const int*   nbr    = (const int*)d_in[2];
    const float* weight = (const float*)d_in[3];
    const float* kpts   = (const float*)d_in[4];
    const float* gamma  = (const float*)d_in[5];
    const float* beta   = (const float*)d_in[6];
    float* out = (float*)d_out;

    cudaFuncSetAttribute(kpconv_fused,
                         cudaFuncAttributeMaxDynamicSharedMemorySize, SMEM_TOTAL);

    prep_kernel<<<NPTS / 256 + 8, 256>>>(xyz, weight);
    kpconv_fused<<<NPTS / PTS_BLK, NTHREADS, SMEM_TOTAL>>>(feats, nbr, kpts);
    finalize_kernel<<<(NPTS * COUT / 4) / 256, 256>>>(out, gamma, beta);
}

// round 14
// speedup vs baseline: 2.0981x; 2.0981x over previous
#include <cuda_runtime.h>
#include <cuda_fp16.h>
#include <stdint.h>

#define NPTS 131072
#define NM   34
#define NK   15
#define CIN  32
#define COUT 64
#define KTOT 480                 // NK * CIN
#define INV_SIGMA 25.0f          // 1 / 0.04
#define BN_EPS 1e-5f
#define NEG_SLOPE 0.2f

// ---- device scratch (no allocations allowed) ----
__device__ __align__(16) __half g_wf_hi[(size_t)NPTS * KTOT];   // 126 MB
__device__ __align__(16) __half g_wh_hi[KTOT * COUT];           // 60 KB
__device__ __align__(16) __half g_wh_lo[KTOT * COUT];           // 60 KB
__device__ __align__(16) float4 g_xyz4[NPTS];                   // 2 MB
__device__ float  g_raw[(size_t)NPTS * COUT];                   // 33.5 MB
__device__ float  g_accum[2 * COUT];

// ---- packed f32x2 helpers ----
__device__ __forceinline__ unsigned long long ffma2(unsigned long long a,
                                                    unsigned long long b,
                                                    unsigned long long c) {
    unsigned long long d;
    asm("fma.rn.f32x2 %0, %1, %2, %3;" : "=l"(d) : "l"(a), "l"(b), "l"(c));
    return d;
}
__device__ __forceinline__ unsigned long long pack2(float lo, float hi) {
    unsigned long long d;
    asm("mov.b64 %0, {%1, %2};" : "=l"(d) : "f"(lo), "f"(hi));
    return d;
}
__device__ __forceinline__ void unpack2(unsigned long long v, float& lo, float& hi) {
    asm("mov.b64 {%0, %1}, %2;" : "=f"(lo), "=f"(hi) : "l"(v));
}

// ---- tensor-core / async-copy helpers ----
__device__ __forceinline__ uint32_t smem_u32(const void* p) {
    return (uint32_t)__cvta_generic_to_shared(p);
}
__device__ __forceinline__ void cp16(uint32_t dst, const void* src) {
    asm volatile("cp.async.cg.shared.global [%0], [%1], 16;" :: "r"(dst), "l"(src));
}
#define CP_COMMIT() asm volatile("cp.async.commit_group;")
#define CP_WAIT(n)  asm volatile("cp.async.wait_group %0;" :: "n"(n))

__device__ __forceinline__ void ldm_x4(uint32_t& r0, uint32_t& r1,
                                       uint32_t& r2, uint32_t& r3, uint32_t addr) {
    asm volatile("ldmatrix.sync.aligned.m8n8.x4.shared.b16 {%0,%1,%2,%3}, [%4];"
                 : "=r"(r0), "=r"(r1), "=r"(r2), "=r"(r3) : "r"(addr));
}
__device__ __forceinline__ void ldm_x4_trans(uint32_t& r0, uint32_t& r1,
                                             uint32_t& r2, uint32_t& r3, uint32_t addr) {
    asm volatile("ldmatrix.sync.aligned.m8n8.x4.trans.shared.b16 {%0,%1,%2,%3}, [%4];"
                 : "=r"(r0), "=r"(r1), "=r"(r2), "=r"(r3) : "r"(addr));
}
__device__ __forceinline__ void mma16816(float& c0, float& c1, float& c2, float& c3,
                                         uint32_t a0, uint32_t a1, uint32_t a2, uint32_t a3,
                                         uint32_t b0, uint32_t b1) {
    asm volatile("mma.sync.aligned.m16n8k16.row.col.f32.f16.f16.f32 "
                 "{%0,%1,%2,%3}, {%4,%5,%6,%7}, {%8,%9}, {%0,%1,%2,%3};"
                 : "+f"(c0), "+f"(c1), "+f"(c2), "+f"(c3)
                 : "r"(a0), "r"(a1), "r"(a2), "r"(a3), "r"(b0), "r"(b1));
}

// ================= stage 0: repack xyz + split W + zero accum =================
__global__ __launch_bounds__(256)
void prep_kernel(const float* __restrict__ xyz,
                 const float* __restrict__ weight)
{
    const int b = blockIdx.x;
    if (b < NPTS / 256) {
        int n = b * 256 + threadIdx.x;
        g_xyz4[n] = make_float4(xyz[n * 3 + 0], xyz[n * 3 + 1], xyz[n * 3 + 2], 0.f);
    } else {
        int wb = b - NPTS / 256;                 // 0..7
        for (int j = 0; j < (KTOT * COUT) / (8 * 256); j++) {
            int i = (wb * (KTOT * COUT) / 8) + j * 256 + threadIdx.x;
            float w = weight[i];
            __half h = __float2half_rn(w);
            g_wh_hi[i] = h;
            g_wh_lo[i] = __float2half_rn(w - __half2float(h));
        }
        if (wb == 0 && threadIdx.x < 2 * COUT) g_accum[threadIdx.x] = 0.f;
    }
}

// ================= stage 1: wf (fp16 hi plane) =================
// 128 threads, 4 warps, 2 points per warp, lane = input channel
__global__ __launch_bounds__(128)
void kpconv_wf(const float* __restrict__ feats,
               const int*   __restrict__ nbr,
               const float* __restrict__ kpts)
{
    __shared__ float4 sm_kc[16];
    __shared__ float4 sm_nb[4][NM];
    __shared__ int    sm_idx[4][NM];
    __shared__ int    sm_act[4][NM];
    __shared__ int    sm_cm[4][36];                    // compacted active m list
    __shared__ __align__(16) float sm_w[4][NM * 16];   // m-major, k stride 1

    const int tid  = threadIdx.x;
    const int lane = tid & 31;
    const int warp = tid >> 5;

    if (tid < 16) {
        float4 kc = make_float4(0.f, 0.f, 0.f, 0.f);
        if (tid < NK) {
            kc.x = kpts[tid * 3 + 0];
            kc.y = kpts[tid * 3 + 1];
            kc.z = kpts[tid * 3 + 2];
        }
        sm_kc[tid] = kc;
    }
    __syncthreads();

    #pragma unroll
    for (int i = 0; i < 2; i++) {
        const int n = blockIdx.x * 8 + warp * 2 + i;

        const float4 c4 = g_xyz4[n];              // broadcast LDG.128

        // neighbor prep: ONE vector load per neighbor
        #pragma unroll
        for (int j = 0; j < 2; j++) {
            int m = j * 32 + lane;
            if (m < NM) {
                int idx = nbr[n * NM + m];
                int ci  = (idx < NPTS) ? idx : 0;          // shadow guard
                float4 p = __ldg(&g_xyz4[ci]);
                float4 v = make_float4(p.x - c4.x, p.y - c4.y, p.z - c4.z, 0.f);
                if (idx >= NPTS) { v.x = 1e6f; v.y = 1e6f; v.z = 1e6f; }
                sm_nb[warp][m]  = v;
                sm_idx[warp][m] = ci;
            }
        }
        __syncwarp();

        // influence weights w[m*16+k] + per-m activity mask
        #pragma unroll
        for (int it = 0; it < 17; it++) {
            int p = it * 32 + lane;                        // 0..543
            int m = p >> 4;
            int k = p & 15;
            float4 nb = sm_nb[warp][m];
            float4 kc = sm_kc[k];
            float dx = nb.x - kc.x;
            float dy = nb.y - kc.y;
            float dz = nb.z - kc.z;
            float d2 = fmaf(dx, dx, fmaf(dy, dy, dz * dz));
            float w  = fmaf(sqrtf(d2), -INV_SIGMA, 1.f);
            bool on  = (w > 0.f) && (k < 15);
            unsigned bal = __ballot_sync(0xffffffffu, on);
            sm_w[warp][p] = on ? w : 0.f;
            if (lane == 0)  sm_act[warp][it * 2]     = (int)(bal & 0xffffu);
            if (lane == 16) sm_act[warp][it * 2 + 1] = (int)(bal >> 16);
        }
        __syncwarp();

        // ---- compact the active-m list (warp-uniform count) ----
        int cnt = 0;
        #pragma unroll
        for (int j = 0; j < 2; j++) {
            int m = j * 32 + lane;
            bool on = (m < NM) && (sm_act[warp][m] != 0);
            unsigned bal = __ballot_sync(0xffffffffu, on);
            if (on) {
                int pos = cnt + __popc(bal & ((1u << lane) - 1u));
                sm_cm[warp][pos] = m;
            }
            cnt += __popc(bal);
        }
        __syncwarp();

        // ---- accumulation over compacted list, 4-deep load batching ----
        unsigned long long wf2[8];
        #pragma unroll
        for (int j = 0; j < 8; j++) wf2[j] = 0ull;

        for (int j0 = 0; j0 < cnt; j0 += 4) {
            float f[4];
            int   mm[4];
            #pragma unroll
            for (int t = 0; t < 4; t++) {
                int jt = j0 + t;
                bool v = (jt < cnt);
                mm[t] = sm_cm[warp][v ? jt : j0];
                f[t]  = 0.f;
                if (v)
                    f[t] = __ldg(&feats[(size_t)sm_idx[warp][mm[t]] * CIN + lane]);
            }
            #pragma unroll
            for (int t = 0; t < 4; t++) {
                unsigned long long ff = pack2(f[t], f[t]);
                const ulonglong2* wp =
                    (const ulonglong2*)&sm_w[warp][mm[t] * 16];
                #pragma unroll
                for (int q = 0; q < 4; q++) {
                    ulonglong2 wv = wp[q];                 // LDS.128
                    wf2[2 * q]     = ffma2(ff, wv.x, wf2[2 * q]);
                    wf2[2 * q + 1] = ffma2(ff, wv.y, wf2[2 * q + 1]);
                }
            }
        }

        // fp16 store (k-major global layout: col = k*32 + lane)
        __half* dh = &g_wf_hi[(size_t)n * KTOT + lane];
        #pragma unroll
        for (int j = 0; j < 8; j++) {
            float a, b;
            unpack2(wf2[j], a, b);
            dh[(2 * j) * 32] = __float2half_rn(a);
            if (j < 7) dh[(2 * j + 1) * 32] = __float2half_rn(b);
        }
        __syncwarp();
    }
}

// ================= stage 2: pipelined HMMA GEMM [N,480]x[480,64] =================
// 256 threads = 8 warps; warp w owns rows [16w,16w+16), all 64 cols.
__global__ __launch_bounds__(256)
void gemm_kernel()
{
    __shared__ __align__(16) __half As[2][128][40];
    __shared__ __align__(16) __half Bh[2][32][72];
    __shared__ __align__(16) __half Bl[2][32][72];
    __shared__ float sm_bn[2 * COUT];

    const int tid  = threadIdx.x;
    const int lane = tid & 31;
    const int warp = tid >> 5;
    const int row0 = blockIdx.x * 128;

    if (tid < 2 * COUT) sm_bn[tid] = 0.f;

    float acc[8][4];
    #pragma unroll
    for (int nt = 0; nt < 8; nt++)
        #pragma unroll
        for (int c = 0; c < 4; c++) acc[nt][c] = 0.f;

    // ldmatrix lane address bases (per buffer)
    const int arow = warp * 16 + (lane & 15);
    const int acol = (lane >> 4) * 8;
    const uint32_t aB0 = smem_u32(&As[0][arow][acol]);
    const uint32_t aB1 = smem_u32(&As[1][arow][acol]);
    const int brow = ((lane >> 3) & 1) * 8 + (lane & 7);
    const int bcol = (lane >> 4) * 8;
    const uint32_t bhB0 = smem_u32(&Bh[0][brow][bcol]);
    const uint32_t bhB1 = smem_u32(&Bh[1][brow][bcol]);
    const uint32_t blB0 = smem_u32(&Bl[0][brow][bcol]);
    const uint32_t blB1 = smem_u32(&Bl[1][brow][bcol]);

    const int br = tid >> 3, bq = tid & 7;

    #define LOAD_TILE(kc, buf)                                                  \
    do {                                                                        \
        _Pragma("unroll")                                                       \
        for (int j = 0; j < 2; j++) {                                           \
            int c = tid + j * 256;                                              \
            int r = c >> 2, q = c & 3;                                          \
            cp16(smem_u32(&As[buf][r][q * 8]),                                  \
                 &g_wf_hi[(size_t)(row0 + r) * KTOT + (kc) * 32 + q * 8]);      \
        }                                                                       \
        cp16(smem_u32(&Bh[buf][br][bq * 8]),                                    \
             &g_wh_hi[((kc) * 32 + br) * COUT + bq * 8]);                       \
        cp16(smem_u32(&Bl[buf][br][bq * 8]),                                    \
             &g_wh_lo[((kc) * 32 + br) * COUT + bq * 8]);                       \
    } while (0)

    LOAD_TILE(0, 0);
    CP_COMMIT();

    for (int kc = 0; kc < KTOT / 32; kc++) {
        const int buf = kc & 1;
        if (kc < KTOT / 32 - 1) {
            LOAD_TILE(kc + 1, buf ^ 1);
            CP_COMMIT();
            CP_WAIT(1);
        } else {
            CP_WAIT(0);
        }
        __syncthreads();

        const uint32_t aBase  = buf ? aB1 : aB0;
        const uint32_t bhBase = buf ? bhB1 : bhB0;
        const uint32_t blBase = buf ? blB1 : blB0;

        #pragma unroll
        for (int ks = 0; ks < 2; ks++) {
            uint32_t ah[4];
            ldm_x4(ah[0], ah[1], ah[2], ah[3], aBase + ks * 32);   // +16 halves

            uint32_t bh[8][2], bl[8][2];
            #pragma unroll
            for (int np = 0; np < 4; np++) {
                uint32_t r0, r1, r2, r3;
                ldm_x4_trans(r0, r1, r2, r3, bhBase + ks * 16 * 144 + np * 32);
                bh[2 * np][0] = r0; bh[2 * np][1] = r1;
                bh[2 * np + 1][0] = r2; bh[2 * np + 1][1] = r3;
                ldm_x4_trans(r0, r1, r2, r3, blBase + ks * 16 * 144 + np * 32);
                bl[2 * np][0] = r0; bl[2 * np][1] = r1;
                bl[2 * np + 1][0] = r2; bl[2 * np + 1][1] = r3;
            }
            #pragma unroll
            for (int nt = 0; nt < 8; nt++) {
                mma16816(acc[nt][0], acc[nt][1], acc[nt][2], acc[nt][3],
                         ah[0], ah[1], ah[2], ah[3], bh[nt][0], bh[nt][1]);
                mma16816(acc[nt][0], acc[nt][1], acc[nt][2], acc[nt][3],
                         ah[0], ah[1], ah[2], ah[3], bl[nt][0], bl[nt][1]);
            }
        }
        __syncthreads();
    }

    // epilogue: write raw out + BN partial sums
    const int g8 = lane >> 2, t4 = lane & 3;
    const int rA = row0 + warp * 16 + g8;
    const int rB = rA + 8;
    float lsum[16], lsq[16];
    #pragma unroll
    for (int nt = 0; nt < 8; nt++) {
        int col = nt * 8 + 2 * t4;
        *(float2*)&g_raw[(size_t)rA * COUT + col] = make_float2(acc[nt][0], acc[nt][1]);
        *(float2*)&g_raw[(size_t)rB * COUT + col] = make_float2(acc[nt][2], acc[nt][3]);
        lsum[2 * nt]     = acc[nt][0] + acc[nt][2];
        lsum[2 * nt + 1] = acc[nt][1] + acc[nt][3];
        lsq[2 * nt]      = fmaf(acc[nt][0], acc[nt][0], acc[nt][2] * acc[nt][2]);
        lsq[2 * nt + 1]  = fmaf(acc[nt][1], acc[nt][1], acc[nt][3] * acc[nt][3]);
    }
    #pragma unroll
    for (int mask = 4; mask <= 16; mask <<= 1) {
        #pragma unroll
        for (int v = 0; v < 16; v++) {
            lsum[v] += __shfl_xor_sync(0xffffffffu, lsum[v], mask);
            lsq[v]  += __shfl_xor_sync(0xffffffffu, lsq[v],  mask);
        }
    }
    if (g8 == 0) {
        #pragma unroll
        for (int nt = 0; nt < 8; nt++) {
            int col = nt * 8 + 2 * t4;
            atomicAdd(&sm_bn[col],            lsum[2 * nt]);
            atomicAdd(&sm_bn[col + 1],        lsum[2 * nt + 1]);
            atomicAdd(&sm_bn[COUT + col],     lsq[2 * nt]);
            atomicAdd(&sm_bn[COUT + col + 1], lsq[2 * nt + 1]);
        }
    }
    __syncthreads();
    if (tid < 2 * COUT) atomicAdd(&g_accum[tid], sm_bn[tid]);
}

// ================= finalize (computes BN params per-block) =================
__global__ __launch_bounds__(256)
void finalize_kernel(float* __restrict__ out,
                     const float* __restrict__ gamma,
                     const float* __restrict__ beta)
{
    __shared__ float sp[2 * COUT];
    const int t = threadIdx.x;
    if (t < COUT) {
        const float invN = 1.0f / (float)NPTS;
        float mean = g_accum[t] * invN;
        float var  = g_accum[COUT + t] * invN - mean * mean;
        float inv  = rsqrtf(var + BN_EPS);
        float sc   = gamma[t] * inv;
        sp[t]        = sc;
        sp[COUT + t] = fmaf(-mean, sc, beta[t]);
    }
    __syncthreads();

    int i = blockIdx.x * blockDim.x + t;             // over N*64/4 float4s
    float4 v = *(const float4*)&g_raw[(size_t)i * 4];
    int d4 = (i & 15) * 4;
    float x0 = fmaf(v.x, sp[d4 + 0], sp[COUT + d4 + 0]);
    float x1 = fmaf(v.y, sp[d4 + 1], sp[COUT + d4 + 1]);
    float x2 = fmaf(v.z, sp[d4 + 2], sp[COUT + d4 + 2]);
    float x3 = fmaf(v.w, sp[d4 + 3], sp[COUT + d4 + 3]);
    x0 = (x0 >= 0.f) ? x0 : NEG_SLOPE * x0;
    x1 = (x1 >= 0.f) ? x1 : NEG_SLOPE * x1;
    x2 = (x2 >= 0.f) ? x2 : NEG_SLOPE * x2;
    x3 = (x3 >= 0.f) ? x3 : NEG_SLOPE * x3;
    ((float4*)out)[i] = make_float4(x0, x1, x2, x3);
}

extern "C" void kernel_launch(void* const* d_in, const int* in_sizes, int n_in,
                              void* d_out, int out_size)
{
    const float* xyz    = (const float*)d_in[0];
    const float* feats  = (const float*)d_in[1];
    const int*   nbr    = (const int*)d_in[2];
    const float* weight = (const float*)d_in[3];
    const float* kpts   = (const float*)d_in[4];
    const float* gamma  = (const float*)d_in[5];
    const float* beta   = (const float*)d_in[6];
    float* out = (float*)d_out;

    prep_kernel<<<NPTS / 256 + 8, 256>>>(xyz, weight);
    kpconv_wf<<<NPTS / 8, 128>>>(feats, nbr, kpts);
    gemm_kernel<<<NPTS / 128, 256>>>();
    finalize_kernel<<<(NPTS * COUT / 4) / 256, 256>>>(out, gamma, beta);
}